// round 15
// baseline (speedup 1.0000x reference)
#include <cuda_runtime.h>
#include <cstdint>
#include <math.h>

#define NB 8
#define SS 2048
#define DM 1024
#define NH 16
#define DH 64
#define MROWS (NB * SS)
#define ELEMS ((size_t)MROWS * DM)

__device__ float g_Q[ELEMS];             // Q = Q_seq @ WQ (fp32)
__device__ float g_Kp[ELEMS];            // Kp scattered to [b,h,s,dh]
__device__ float g_WTq[DM * DM];         // rna(WQ^T)
__device__ float g_WTk[DM * DM];         // rna(WK^T)
__device__ float g_WTp[DM * DM];         // WP^T (raw)
__device__ float g_WT3[(size_t)NB * DM * DM]; // per-batch rna(kg_b * WP^T)
__device__ float g_WbS[(size_t)NB * NH * NH * DM]; // per-(b,h) qg-scaled WbT [bh][e][d]
__device__ float g_logits[NB * NH * SS];
__device__ float g_qglob[NB * DM];
__device__ float g_kglob[NB * DM];
__device__ float g_WaT[NH * DM];
__device__ float g_WbT[NH * DM];
__device__ float g_smx[NB * NH];
__device__ float g_sinv[NB * NH];
__device__ float g_part[NB * NH * 8 * DH];

// ---------------- helpers ----------------
__device__ __forceinline__ uint32_t smem_u32(const void* p) {
    uint32_t a;
    asm("{ .reg .u64 t; cvta.to.shared.u64 t, %1; cvt.u32.u64 %0, t; }" : "=r"(a) : "l"(p));
    return a;
}
__device__ __forceinline__ void cp_async16(uint32_t s, const void* g) {
    asm volatile("cp.async.cg.shared.global [%0], [%1], 16;" :: "r"(s), "l"(g));
}
__device__ __forceinline__ void cp_commit() { asm volatile("cp.async.commit_group;" ::: "memory"); }
template <int N> __device__ __forceinline__ void cp_wait() {
    asm volatile("cp.async.wait_group %0;" :: "n"(N) : "memory");
}
__device__ __forceinline__ float rna_tf32(float x) {
    float r;
    asm("cvt.rna.tf32.f32 %0, %1;" : "=f"(r) : "f"(x));
    return r;
}
__device__ __forceinline__ void mma_tf32(float* c, const uint32_t* a, const uint32_t* b) {
    asm volatile(
        "mma.sync.aligned.m16n8k8.row.col.f32.tf32.tf32.f32 "
        "{%0,%1,%2,%3}, {%4,%5,%6,%7}, {%8,%9}, {%0,%1,%2,%3};"
        : "+f"(c[0]), "+f"(c[1]), "+f"(c[2]), "+f"(c[3])
        : "r"(a[0]), "r"(a[1]), "r"(a[2]), "r"(a[3]), "r"(b[0]), "r"(b[1]));
}

// ---------------- mma.sync tf32 GEMM core: 128 threads, warp tile 64x64 ----------------
// BM=BN=128, BK=32, 4 warps (2x2), 3-stage cp.async ring, 2 CTAs/SM.
// A may be raw fp32 (HW truncates to tf32); B must be pre-rounded.
#define BKF 32
#define ASTR 36
#define TILE_F (128 * ASTR)
#define STAGE_F (2 * TILE_F)
#define NST 3
#define KITERS (DM / BKF)
#define DYN_SMEM (NST * STAGE_F * 4)

// Shared mainloop: accumulates A[rowM:+128, :] @ Bt[rowN:+128, :]^T into acc.
__device__ __forceinline__ void gemm_core(
    const float* __restrict__ A, const float* __restrict__ Bt,
    int rowM, int rowN, uint32_t sbase, float* smbase,
    int tid, int warpM, int warpN, int grp, int qid,
    float acc[4][8][4])
{
    auto prefetch = [&](int kt, int slot) {
        const uint32_t sA = sbase + (uint32_t)slot * STAGE_F * 4;
        const uint32_t sB = sA + TILE_F * 4;
        const int kbase = kt * BKF;
#pragma unroll
        for (int j = 0; j < 8; j++) {
            const int t = tid + j * 128;
            const int row = t >> 3, g = t & 7;
            cp_async16(sA + (uint32_t)(row * ASTR + g * 4) * 4,
                       A + (size_t)(rowM + row) * DM + kbase + g * 4);
        }
#pragma unroll
        for (int j = 0; j < 8; j++) {
            const int t = tid + j * 128;
            const int row = t >> 3, g = t & 7;
            cp_async16(sB + (uint32_t)(row * ASTR + g * 4) * 4,
                       Bt + (size_t)(rowN + row) * DM + kbase + g * 4);
        }
        cp_commit();
    };

    prefetch(0, 0);
    prefetch(1, 1);

    for (int kt = 0; kt < KITERS; kt++) {
        if (kt < KITERS - 1) cp_wait<1>(); else cp_wait<0>();
        __syncthreads();
        if (kt + 2 < KITERS) prefetch(kt + 2, (kt + 2) % NST);

        const float* As = smbase + (kt % NST) * STAGE_F;
        const float* Bs = As + TILE_F;
#pragma unroll
        for (int ks = 0; ks < 4; ks++) {
            const int c = ks * 8 + qid;
            uint32_t afr[4][4], bfr[8][2];
#pragma unroll
            for (int mt = 0; mt < 4; mt++) {
                const int r = warpM * 64 + mt * 16 + grp;
                afr[mt][0] = __float_as_uint(As[r * ASTR + c]);
                afr[mt][1] = __float_as_uint(As[(r + 8) * ASTR + c]);
                afr[mt][2] = __float_as_uint(As[r * ASTR + c + 4]);
                afr[mt][3] = __float_as_uint(As[(r + 8) * ASTR + c + 4]);
            }
#pragma unroll
            for (int nt = 0; nt < 8; nt++) {
                const int n = warpN * 64 + nt * 8 + grp;
                bfr[nt][0] = __float_as_uint(Bs[n * ASTR + c]);
                bfr[nt][1] = __float_as_uint(Bs[n * ASTR + c + 4]);
            }
#pragma unroll
            for (int mt = 0; mt < 4; mt++)
#pragma unroll
                for (int nt = 0; nt < 8; nt++)
                    mma_tf32(acc[mt][nt], afr[mt], bfr[nt]);
        }
    }
}

// Merged GEMM1+GEMM2: blockIdx.y in [0,128) -> Q = Q_seq@WQ (plain store);
// blockIdx.y in [128,256) -> Kp = K_seq@WK scattered to [b,h,s,dh] (no scale).
__global__ __launch_bounds__(128, 2) void gemm_merged(
    const float* __restrict__ Q_seq, const float* __restrict__ WTq,
    const float* __restrict__ K_seq, const float* __restrict__ WTk,
    float* __restrict__ Qout, float* __restrict__ Kpout)
{
    extern __shared__ float sm[];
    const uint32_t sbase = smem_u32(sm);
    const int tid = threadIdx.x;
    const int wid = tid >> 5, lane = tid & 31;
    const int warpM = wid & 1, warpN = wid >> 1;
    const int grp = lane >> 2, qid = lane & 3;
    const int tileY = blockIdx.y;
    const bool isK = tileY >= 128;
    const int rowM = (tileY & 127) * 128, rowN = blockIdx.x * 128;
    const int bB = rowM >> 11;

    const float* A  = isK ? K_seq : Q_seq;
    const float* Bt = isK ? WTk : WTq;

    float acc[4][8][4];
#pragma unroll
    for (int i = 0; i < 4; i++)
#pragma unroll
        for (int j = 0; j < 8; j++)
#pragma unroll
            for (int l = 0; l < 4; l++) acc[i][j][l] = 0.0f;

    gemm_core(A, Bt, rowM, rowN, sbase, sm, tid, warpM, warpN, grp, qid, acc);

#pragma unroll
    for (int mt = 0; mt < 4; mt++) {
        const int r0 = rowM + warpM * 64 + mt * 16 + grp;
        const int r1 = r0 + 8;
        const int s0 = r0 & (SS - 1), s1 = r1 & (SS - 1);
#pragma unroll
        for (int nt = 0; nt < 8; nt++) {
            const int n = rowN + warpN * 64 + nt * 8 + qid * 2;
            const float* a4 = acc[mt][nt];
            if (!isK) {
                *(float2*)(Qout + (size_t)r0 * DM + n) = make_float2(a4[0], a4[1]);
                *(float2*)(Qout + (size_t)r1 * DM + n) = make_float2(a4[2], a4[3]);
            } else {
                const int h = n >> 6, d = n & 63;
                float* base = Kpout + (((size_t)(bB * NH + h)) << 17) + d;
                *(float2*)(base + (size_t)s0 * DH) = make_float2(a4[0], a4[1]);
                *(float2*)(base + (size_t)s1 * DH) = make_float2(a4[2], a4[3]);
            }
        }
    }
}

// GEMM3: out = Q @ (per-batch B) + Q residual.
__global__ __launch_bounds__(128, 2) void gemm_final(
    const float* __restrict__ A, const float* __restrict__ Bt_all,
    float* __restrict__ C, const float* __restrict__ res)
{
    extern __shared__ float sm[];
    const uint32_t sbase = smem_u32(sm);
    const int tid = threadIdx.x;
    const int wid = tid >> 5, lane = tid & 31;
    const int warpM = wid & 1, warpN = wid >> 1;
    const int grp = lane >> 2, qid = lane & 3;
    const int rowM = blockIdx.y * 128, rowN = blockIdx.x * 128;
    const int bB = rowM >> 11;
    const float* Bt = Bt_all + (size_t)bB * DM * DM;

    float acc[4][8][4];
#pragma unroll
    for (int i = 0; i < 4; i++)
#pragma unroll
        for (int j = 0; j < 8; j++)
#pragma unroll
            for (int l = 0; l < 4; l++) acc[i][j][l] = 0.0f;

    gemm_core(A, Bt, rowM, rowN, sbase, sm, tid, warpM, warpN, grp, qid, acc);

#pragma unroll
    for (int mt = 0; mt < 4; mt++) {
        const int r0 = rowM + warpM * 64 + mt * 16 + grp;
        const int r1 = r0 + 8;
#pragma unroll
        for (int nt = 0; nt < 8; nt++) {
            const int n = rowN + warpN * 64 + nt * 8 + qid * 2;
            const float* a4 = acc[mt][nt];
            const float2 q0 = *(const float2*)(res + (size_t)r0 * DM + n);
            const float2 q1 = *(const float2*)(res + (size_t)r1 * DM + n);
            *(float2*)(C + (size_t)r0 * DM + n) = make_float2(a4[0] + q0.x, a4[1] + q0.y);
            *(float2*)(C + (size_t)r1 * DM + n) = make_float2(a4[2] + q1.x, a4[3] + q1.y);
        }
    }
}

// ---------------- small kernels ----------------
template <bool RNA>
__global__ void transpose_k(const float* __restrict__ W, float* __restrict__ WT)
{
    __shared__ float t[32][33];
    const int x0 = blockIdx.x * 32, y0 = blockIdx.y * 32;
    const int tx = threadIdx.x, ty = threadIdx.y;  // 32 x 8
#pragma unroll
    for (int j = 0; j < 32; j += 8)
        t[ty + j][tx] = W[(size_t)(y0 + ty + j) * DM + x0 + tx];
    __syncthreads();
#pragma unroll
    for (int j = 0; j < 32; j += 8) {
        float v = t[tx][ty + j];
        WT[(size_t)(x0 + ty + j) * DM + y0 + tx] = RNA ? rna_tf32(v) : v;
    }
}

__global__ void transpose_w(const float* __restrict__ W, float* __restrict__ WT)
{
    int i = blockIdx.x * 256 + threadIdx.x;
    if (i < DM * NH) {
        int j = i >> 4, e = i & 15;
        WT[e * DM + j] = W[i];
    }
}

// WT3[b][n][k] = rna( WTp[n][k] * kg[b][k] )
__global__ __launch_bounds__(256) void scale_wt8(
    const float4* __restrict__ WTp, const float* __restrict__ kg,
    float4* __restrict__ WT3)
{
    const size_t i = (size_t)blockIdx.x * 256 + threadIdx.x;  // 2M float4
    const int k4 = (int)(i & 255);
    const int b  = (int)(i >> 18);
    const float4 w = WTp[i & ((1u << 18) - 1)];
    const float4 g = *(const float4*)(kg + (size_t)b * DM + k4 * 4);
    float4 o;
    o.x = rna_tf32(w.x * g.x); o.y = rna_tf32(w.y * g.y);
    o.z = rna_tf32(w.z * g.z); o.w = rna_tf32(w.w * g.w);
    WT3[i] = o;
}

// WbS[bh][e][d] = WbT[e][d] * qg[bh*64 + (d&63)]   (float4 over d)
__global__ __launch_bounds__(256) void scale_wb(
    const float4* __restrict__ WbT, const float* __restrict__ qg,
    float4* __restrict__ WbS)
{
    const size_t i = (size_t)blockIdx.x * 256 + threadIdx.x;  // 128*16*256 float4
    const int d4 = (int)(i & 255);              // d = d4*4
    const int bh = (int)(i >> 12);              // 16 e * 256 d4 per bh
    const float4 w = WbT[i & 4095];
    const float4 g = *(const float4*)(qg + (size_t)bh * DH + ((d4 * 4) & 63));
    float4 o;
    o.x = w.x * g.x; o.y = w.y * g.y; o.z = w.z * g.z; o.w = w.w * g.w;
    WbS[i] = o;
}

// ---------------- row_logits: smem weights + 1024 blocks ----------------
// PERH=0: one shared WT[16][1024] for all rows.
// PERH=1: weight set selected per block as WT + bh*16*1024 (h constant per block).
#define LROWS 16
#define LOGIT_SMEM (NH * DM * 4)   // 65536
template <int PERH>
__global__ __launch_bounds__(256) void row_logits_sm(
    const float* __restrict__ rows, const float* __restrict__ WT,
    float* __restrict__ logits, float scaleF)
{
    extern __shared__ float4 w4[];   // [16 * 256] float4
    const int tid = threadIdx.x;
    const int wid = tid >> 5, lane = tid & 31;
    const int rbase = blockIdx.x * LROWS;

    const float4* wt4 = (const float4*)WT;
    if (PERH) {
        const int r = rbase;
        const int b = r >> 11, h = (r & (SS - 1)) >> 7;
        wt4 += (size_t)(b * NH + h) * (NH * DM / 4);
    }
#pragma unroll
    for (int i = 0; i < NH; i++)
        w4[i * 256 + tid] = wt4[i * 256 + tid];
    __syncthreads();

    const float4* w0 = w4 + (size_t)wid * 256;
    const float4* w1 = w4 + (size_t)(wid + 8) * 256;

    for (int rr = 0; rr < LROWS; rr++) {
        const int r = rbase + rr;
        const float4* rp = (const float4*)(rows + (size_t)r * DM);
        float4 v[8];
#pragma unroll
        for (int j = 0; j < 8; j++) v[j] = rp[j * 32 + lane];

        float a0 = 0.0f, a1 = 0.0f;
#pragma unroll
        for (int j = 0; j < 8; j++) {
            const float4 u0 = w0[j * 32 + lane];
            const float4 u1 = w1[j * 32 + lane];
            a0 = fmaf(v[j].x, u0.x, a0); a0 = fmaf(v[j].y, u0.y, a0);
            a0 = fmaf(v[j].z, u0.z, a0); a0 = fmaf(v[j].w, u0.w, a0);
            a1 = fmaf(v[j].x, u1.x, a1); a1 = fmaf(v[j].y, u1.y, a1);
            a1 = fmaf(v[j].z, u1.z, a1); a1 = fmaf(v[j].w, u1.w, a1);
        }
#pragma unroll
        for (int o = 16; o; o >>= 1) {
            a0 += __shfl_xor_sync(0xffffffffu, a0, o);
            a1 += __shfl_xor_sync(0xffffffffu, a1, o);
        }
        if (lane == 0) {
            const int b = r >> 11, s = r & (SS - 1);
            logits[((size_t)(b * NH + wid)) * SS + s]     = a0 * scaleF;
            logits[((size_t)(b * NH + wid + 8)) * SS + s] = a1 * scaleF;
        }
    }
}

// ---------------- softmax stats ----------------
__global__ __launch_bounds__(256) void softmax_stats(
    const float* __restrict__ logits, float* __restrict__ smx, float* __restrict__ sinv)
{
    const int bh = blockIdx.x;
    const float* lg = logits + (size_t)bh * SS;
    __shared__ float redm[8], reds[8];
    const int tid = threadIdx.x;
    const int warp = tid >> 5, lane = tid & 31;

    float m = -1e30f;
    for (int s = tid; s < SS; s += 256) m = fmaxf(m, lg[s]);
#pragma unroll
    for (int o = 16; o; o >>= 1) m = fmaxf(m, __shfl_xor_sync(0xffffffffu, m, o));
    if (lane == 0) redm[warp] = m;
    __syncthreads();
    float mm = redm[0];
#pragma unroll
    for (int i = 1; i < 8; i++) mm = fmaxf(mm, redm[i]);

    float sum = 0.0f;
    for (int s = tid; s < SS; s += 256) sum += __expf(lg[s] - mm);
#pragma unroll
    for (int o = 16; o; o >>= 1) sum += __shfl_xor_sync(0xffffffffu, sum, o);
    if (lane == 0) reds[warp] = sum;
    __syncthreads();
    if (tid == 0) {
        float ss = 0.0f;
#pragma unroll
        for (int i = 0; i < 8; i++) ss += reds[i];
        smx[bh] = mm;
        sinv[bh] = 1.0f / ss;
    }
}

// ---------------- pool partial: 8 s-chunks x 128 bh blocks ----------------
__global__ __launch_bounds__(256) void pool_partial(
    const float* __restrict__ logits, const float* __restrict__ src,
    const float* __restrict__ smx, const float* __restrict__ sinv,
    size_t bStride, size_t hStride, size_t sStride,
    float* __restrict__ partial)
{
    const int bid = blockIdx.x;
    const int bh = bid >> 3, ck = bid & 7;
    const int b = bh >> 4, h = bh & 15;
    const float* lg = logits + (size_t)bh * SS;
    const float mx = smx[bh], inv = sinv[bh];

    const int tid = threadIdx.x;
    const int d4 = tid & 15, sg = tid >> 4;
    const int s0 = ck * 256;

    __shared__ float4 red4[16][16];

    const float* sp = src + (size_t)b * bStride + (size_t)h * hStride + d4 * 4;
    float4 acc = make_float4(0.f, 0.f, 0.f, 0.f);
#pragma unroll
    for (int i = 0; i < 16; i++) {
        const int s = s0 + sg + i * 16;
        const float w = __expf(lg[s] - mx) * inv;
        const float4 v = *(const float4*)(sp + (size_t)s * sStride);
        acc.x = fmaf(w, v.x, acc.x); acc.y = fmaf(w, v.y, acc.y);
        acc.z = fmaf(w, v.z, acc.z); acc.w = fmaf(w, v.w, acc.w);
    }
    red4[sg][d4] = acc;
    __syncthreads();
    if (sg == 0) {
        float4 t = red4[0][d4];
#pragma unroll
        for (int g = 1; g < 16; g++) {
            const float4 u = red4[g][d4];
            t.x += u.x; t.y += u.y; t.z += u.z; t.w += u.w;
        }
        *(float4*)(partial + (size_t)bid * DH + d4 * 4) = t;
    }
}

// ---------------- pool reduce: sum 8 chunks (optionally * qg elementwise) ----------------
template <int MUL>
__global__ __launch_bounds__(64) void pool_reduce(
    const float* __restrict__ partial, const float* __restrict__ qg,
    float* __restrict__ out)
{
    const int bh = blockIdx.x, d = threadIdx.x;
    const float* p = partial + (size_t)bh * 8 * DH + d;
    float t = 0.0f;
#pragma unroll
    for (int ck = 0; ck < 8; ck++) t += p[ck * DH];
    if (MUL) t *= qg[(size_t)bh * DH + d];
    out[(size_t)bh * DH + d] = t;
}

// ---------------------------------------------------------------------------
extern "C" void kernel_launch(void* const* d_in, const int* in_sizes, int n_in,
                              void* d_out, int out_size)
{
    const float* Q_seq = (const float*)d_in[0];
    const float* K_seq = (const float*)d_in[1];
    const float* WQ = (const float*)d_in[3];
    const float* WK = (const float*)d_in[4];
    const float* Wa = (const float*)d_in[5];
    const float* Wb = (const float*)d_in[6];
    const float* WP = (const float*)d_in[7];
    float* out = (float*)d_out;

    float *pQ, *pKp, *pWTq, *pWTk, *pWTp, *pWT3, *pWbS, *pLg, *pQg, *pKg;
    float *pWaT, *pWbT, *pMx, *pInv, *pPart;
    cudaGetSymbolAddress((void**)&pQ,   g_Q);
    cudaGetSymbolAddress((void**)&pKp,  g_Kp);
    cudaGetSymbolAddress((void**)&pWTq, g_WTq);
    cudaGetSymbolAddress((void**)&pWTk, g_WTk);
    cudaGetSymbolAddress((void**)&pWTp, g_WTp);
    cudaGetSymbolAddress((void**)&pWT3, g_WT3);
    cudaGetSymbolAddress((void**)&pWbS, g_WbS);
    cudaGetSymbolAddress((void**)&pLg,  g_logits);
    cudaGetSymbolAddress((void**)&pQg,  g_qglob);
    cudaGetSymbolAddress((void**)&pKg,  g_kglob);
    cudaGetSymbolAddress((void**)&pWaT, g_WaT);
    cudaGetSymbolAddress((void**)&pWbT, g_WbT);
    cudaGetSymbolAddress((void**)&pMx,  g_smx);
    cudaGetSymbolAddress((void**)&pInv, g_sinv);
    cudaGetSymbolAddress((void**)&pPart, g_part);

    cudaFuncSetAttribute(gemm_merged, cudaFuncAttributeMaxDynamicSharedMemorySize, DYN_SMEM);
    cudaFuncSetAttribute(gemm_final,  cudaFuncAttributeMaxDynamicSharedMemorySize, DYN_SMEM);
    cudaFuncSetAttribute(row_logits_sm<0>, cudaFuncAttributeMaxDynamicSharedMemorySize, LOGIT_SMEM);
    cudaFuncSetAttribute(row_logits_sm<1>, cudaFuncAttributeMaxDynamicSharedMemorySize, LOGIT_SMEM);

    const float scaleF = 0.125f;
    const dim3 mgrid(DM / 128, 256);             // merged: (8, 256)
    const dim3 ggrid(DM / 128, MROWS / 128);     // final:  (8, 128)
    const dim3 tgrid(32, 32), tblk(32, 8);

    // 0. weight prep
    transpose_w<<<(DM * NH + 255) / 256, 256>>>(Wa, pWaT);
    transpose_w<<<(DM * NH + 255) / 256, 256>>>(Wb, pWbT);
    transpose_k<true><<<tgrid, tblk>>>(WQ, pWTq);
    transpose_k<true><<<tgrid, tblk>>>(WK, pWTk);
    transpose_k<false><<<tgrid, tblk>>>(WP, pWTp);

    // 1. Q = Q_seq@WQ  and  Kp = K_seq@WK (scattered [b,h,s,dh]) — one launch
    gemm_merged<<<mgrid, 128, DYN_SMEM>>>(Q_seq, pWTq, K_seq, pWTk, pQ, pKp);

    // 2. alpha = softmax(Q @ Wa * scale); q_glob = pool(alpha, Qh)
    row_logits_sm<0><<<MROWS / LROWS, 256, LOGIT_SMEM>>>(pQ, pWaT, pLg, scaleF);
    softmax_stats<<<NB * NH, 256>>>(pLg, pMx, pInv);
    pool_partial<<<NB * NH * 8, 256>>>(pLg, pQ, pMx, pInv,
                                       (size_t)SS * DM, (size_t)DH, (size_t)DM, pPart);
    pool_reduce<0><<<NB * NH, 64>>>(pPart, nullptr, pQg);

    // 3. beta logits = Kp_D @ (qg-scaled Wb per (b,h))   [QAK never materialized]
    scale_wb<<<(unsigned)((size_t)NB * NH * NH * DM / 4 / 256), 256>>>(
        (const float4*)pWbT, pQg, (float4*)pWbS);
    row_logits_sm<1><<<MROWS / LROWS, 256, LOGIT_SMEM>>>(pKp, pWbS, pLg, scaleF);

    // 4. k_glob = pool(beta, Kp) ⊙ q_glob
    softmax_stats<<<NB * NH, 256>>>(pLg, pMx, pInv);
    pool_partial<<<NB * NH * 8, 256>>>(pLg, pKp, pMx, pInv,
                                       (size_t)NH * SS * DH, (size_t)SS * DH, (size_t)DH, pPart);
    pool_reduce<1><<<NB * NH, 64>>>(pPart, pQg, pKg);

    // 5. out = Q @ (diag(kg_b) WP) + Q
    scale_wt8<<<(unsigned)((size_t)NB * DM * DM / 4 / 256), 256>>>(
        (const float4*)pWTp, pKg, (float4*)pWT3);
    gemm_final<<<ggrid, 128, DYN_SMEM>>>(pQ, pWT3, out, pQ);
}

// round 16
// speedup vs baseline: 1.0430x; 1.0430x over previous
#include <cuda_runtime.h>
#include <cstdint>
#include <math.h>

#define NB 8
#define SS 2048
#define DM 1024
#define NH 16
#define DH 64
#define MROWS (NB * SS)
#define ELEMS ((size_t)MROWS * DM)

__device__ float g_Q[ELEMS];             // Q = Q_seq @ WQ (fp32)
__device__ float g_QAK[ELEMS];           // QAK [b,h,s,dh]
__device__ float g_WTq[DM * DM];         // rna(WQ^T)
__device__ float g_WTk[DM * DM];         // rna(WK^T)
__device__ float g_WTp[DM * DM];         // WP^T (raw)
__device__ float g_WT3[(size_t)NB * DM * DM]; // per-batch rna(kg_b * WP^T)
__device__ float g_logits[NB * NH * SS];
__device__ float g_qglob[NB * DM];
__device__ float g_kglob[NB * DM];
__device__ float g_WaT[NH * DM];
__device__ float g_WbT[NH * DM];
__device__ float g_part[NB * NH * 8 * DH];

// ---------------- helpers ----------------
__device__ __forceinline__ uint32_t smem_u32(const void* p) {
    uint32_t a;
    asm("{ .reg .u64 t; cvta.to.shared.u64 t, %1; cvt.u32.u64 %0, t; }" : "=r"(a) : "l"(p));
    return a;
}
__device__ __forceinline__ void cp_async16(uint32_t s, const void* g) {
    asm volatile("cp.async.cg.shared.global [%0], [%1], 16;" :: "r"(s), "l"(g));
}
__device__ __forceinline__ void cp_commit() { asm volatile("cp.async.commit_group;" ::: "memory"); }
template <int N> __device__ __forceinline__ void cp_wait() {
    asm volatile("cp.async.wait_group %0;" :: "n"(N) : "memory");
}
__device__ __forceinline__ float rna_tf32(float x) {
    float r;
    asm("cvt.rna.tf32.f32 %0, %1;" : "=f"(r) : "f"(x));
    return r;
}
__device__ __forceinline__ void mma_tf32(float* c, const uint32_t* a, const uint32_t* b) {
    asm volatile(
        "mma.sync.aligned.m16n8k8.row.col.f32.tf32.tf32.f32 "
        "{%0,%1,%2,%3}, {%4,%5,%6,%7}, {%8,%9}, {%0,%1,%2,%3};"
        : "+f"(c[0]), "+f"(c[1]), "+f"(c[2]), "+f"(c[3])
        : "r"(a[0]), "r"(a[1]), "r"(a[2]), "r"(a[3]), "r"(b[0]), "r"(b[1]));
}

// ---------------- mma.sync tf32 GEMM: 128 threads, warp tile 64x64 (R14 verbatim) ----------------
// C[M,N] = A[M,K] @ Bt[N,K]^T ; M=16384, N=1024, K=1024.
// BM=BN=128, BK=32, 4 warps (2x2), 3-stage cp.async ring, 2 CTAs/SM.
// A may be raw fp32 (HW truncates to tf32); B must be pre-rounded.
#define BKF 32
#define ASTR 36
#define TILE_F (128 * ASTR)
#define STAGE_F (2 * TILE_F)
#define NST 3
#define KITERS (DM / BKF)
#define DYN_SMEM (NST * STAGE_F * 4)

// MODE 0: plain store. MODE 1: scale by aux[b,n], scatter to [b,h,s,dh].
// MODE 2: + aux residual, B selected per batch (Bt + b*DM*DM).
template <int MODE>
__global__ __launch_bounds__(128, 2) void gemm_mma(
    const float* __restrict__ A, const float* __restrict__ Bt_in,
    float* __restrict__ C, const float* __restrict__ aux)
{
    extern __shared__ float sm[];
    const uint32_t sbase = smem_u32(sm);
    const int tid = threadIdx.x;
    const int wid = tid >> 5, lane = tid & 31;
    const int warpM = wid & 1, warpN = wid >> 1;      // 2 x 2 warp grid, tile 64x64
    const int grp = lane >> 2, qid = lane & 3;
    const int rowM = blockIdx.y * 128, rowN = blockIdx.x * 128;
    const int bB = rowM >> 11;
    const float* Bt = (MODE == 2) ? Bt_in + (size_t)bB * DM * DM : Bt_in;

    float acc[4][8][4];
#pragma unroll
    for (int i = 0; i < 4; i++)
#pragma unroll
        for (int j = 0; j < 8; j++)
#pragma unroll
            for (int l = 0; l < 4; l++) acc[i][j][l] = 0.0f;

    auto prefetch = [&](int kt, int slot) {
        const uint32_t sA = sbase + (uint32_t)slot * STAGE_F * 4;
        const uint32_t sB = sA + TILE_F * 4;
        const int kbase = kt * BKF;
#pragma unroll
        for (int j = 0; j < 8; j++) {
            const int t = tid + j * 128;
            const int row = t >> 3, g = t & 7;
            cp_async16(sA + (uint32_t)(row * ASTR + g * 4) * 4,
                       A + (size_t)(rowM + row) * DM + kbase + g * 4);
        }
#pragma unroll
        for (int j = 0; j < 8; j++) {
            const int t = tid + j * 128;
            const int row = t >> 3, g = t & 7;
            cp_async16(sB + (uint32_t)(row * ASTR + g * 4) * 4,
                       Bt + (size_t)(rowN + row) * DM + kbase + g * 4);
        }
        cp_commit();
    };

    prefetch(0, 0);
    prefetch(1, 1);

    for (int kt = 0; kt < KITERS; kt++) {
        if (kt < KITERS - 1) cp_wait<1>(); else cp_wait<0>();
        __syncthreads();
        if (kt + 2 < KITERS) prefetch(kt + 2, (kt + 2) % NST);

        const float* As = sm + (kt % NST) * STAGE_F;
        const float* Bs = As + TILE_F;
#pragma unroll
        for (int ks = 0; ks < 4; ks++) {
            const int c = ks * 8 + qid;
            uint32_t afr[4][4], bfr[8][2];
#pragma unroll
            for (int mt = 0; mt < 4; mt++) {
                const int r = warpM * 64 + mt * 16 + grp;
                afr[mt][0] = __float_as_uint(As[r * ASTR + c]);
                afr[mt][1] = __float_as_uint(As[(r + 8) * ASTR + c]);
                afr[mt][2] = __float_as_uint(As[r * ASTR + c + 4]);
                afr[mt][3] = __float_as_uint(As[(r + 8) * ASTR + c + 4]);
            }
#pragma unroll
            for (int nt = 0; nt < 8; nt++) {
                const int n = warpN * 64 + nt * 8 + grp;
                bfr[nt][0] = __float_as_uint(Bs[n * ASTR + c]);
                bfr[nt][1] = __float_as_uint(Bs[n * ASTR + c + 4]);
            }
#pragma unroll
            for (int mt = 0; mt < 4; mt++)
#pragma unroll
                for (int nt = 0; nt < 8; nt++)
                    mma_tf32(acc[mt][nt], afr[mt], bfr[nt]);
        }
    }

    // Epilogue
#pragma unroll
    for (int mt = 0; mt < 4; mt++) {
        const int r0 = rowM + warpM * 64 + mt * 16 + grp;
        const int r1 = r0 + 8;
        const int s0 = r0 & (SS - 1), s1 = r1 & (SS - 1);
#pragma unroll
        for (int nt = 0; nt < 8; nt++) {
            const int n = rowN + warpN * 64 + nt * 8 + qid * 2;
            const float* a4 = acc[mt][nt];
            if (MODE == 0) {
                *(float2*)(C + (size_t)r0 * DM + n) = make_float2(a4[0], a4[1]);
                *(float2*)(C + (size_t)r1 * DM + n) = make_float2(a4[2], a4[3]);
            } else if (MODE == 1) {
                const int h = n >> 6, d = n & 63;
                const float2 g = *(const float2*)(aux + (size_t)bB * DM + n);
                float* base = C + (((size_t)(bB * NH + h)) << 17) + d;  // *2048*64
                *(float2*)(base + (size_t)s0 * DH) = make_float2(a4[0] * g.x, a4[1] * g.y);
                *(float2*)(base + (size_t)s1 * DH) = make_float2(a4[2] * g.x, a4[3] * g.y);
            } else {
                const float2 q0 = *(const float2*)(aux + (size_t)r0 * DM + n);
                const float2 q1 = *(const float2*)(aux + (size_t)r1 * DM + n);
                *(float2*)(C + (size_t)r0 * DM + n) = make_float2(a4[0] + q0.x, a4[1] + q0.y);
                *(float2*)(C + (size_t)r1 * DM + n) = make_float2(a4[2] + q1.x, a4[3] + q1.y);
            }
        }
    }
}

// ---------------- small kernels ----------------
// merged weight transposes: z=0 WQ->rna, z=1 WK->rna, z=2 WP->raw
__global__ void transpose_k3(
    const float* __restrict__ WQ, const float* __restrict__ WK,
    const float* __restrict__ WP,
    float* __restrict__ WTq, float* __restrict__ WTk, float* __restrict__ WTp)
{
    __shared__ float t[32][33];
    const int z = blockIdx.z;
    const float* W = (z == 0) ? WQ : (z == 1) ? WK : WP;
    float* WT      = (z == 0) ? WTq : (z == 1) ? WTk : WTp;
    const bool rna = (z < 2);

    const int x0 = blockIdx.x * 32, y0 = blockIdx.y * 32;
    const int tx = threadIdx.x, ty = threadIdx.y;  // 32 x 8
#pragma unroll
    for (int j = 0; j < 32; j += 8)
        t[ty + j][tx] = W[(size_t)(y0 + ty + j) * DM + x0 + tx];
    __syncthreads();
#pragma unroll
    for (int j = 0; j < 32; j += 8) {
        float v = t[tx][ty + j];
        WT[(size_t)(x0 + ty + j) * DM + y0 + tx] = rna ? rna_tf32(v) : v;
    }
}

// merged small-weight transposes: y=0 Wa, y=1 Wb
__global__ void transpose_w2(
    const float* __restrict__ Wa, const float* __restrict__ Wb,
    float* __restrict__ WaT, float* __restrict__ WbT)
{
    const float* W = blockIdx.y ? Wb : Wa;
    float* WT      = blockIdx.y ? WbT : WaT;
    int i = blockIdx.x * 256 + threadIdx.x;
    if (i < DM * NH) {
        int j = i >> 4, e = i & 15;
        WT[e * DM + j] = W[i];
    }
}

// WT3[b][n][k] = rna( WTp[n][k] * kg[b][k] )
__global__ __launch_bounds__(256) void scale_wt8(
    const float4* __restrict__ WTp, const float* __restrict__ kg,
    float4* __restrict__ WT3)
{
    const size_t i = (size_t)blockIdx.x * 256 + threadIdx.x;  // 2M float4
    const int k4 = (int)(i & 255);
    const int b  = (int)(i >> 18);
    const float4 w = WTp[i & ((1u << 18) - 1)];
    const float4 g = *(const float4*)(kg + (size_t)b * DM + k4 * 4);
    float4 o;
    o.x = rna_tf32(w.x * g.x); o.y = rna_tf32(w.y * g.y);
    o.z = rna_tf32(w.z * g.z); o.w = rna_tf32(w.w * g.w);
    WT3[i] = o;
}

// ---------------- row_logits: smem weights + 1024 blocks ----------------
#define LROWS 16
#define LOGIT_SMEM (NH * DM * 4)   // 65536
__global__ __launch_bounds__(256) void row_logits_sm(
    const float* __restrict__ rows, const float* __restrict__ WT,
    float* __restrict__ logits, float scaleF)
{
    extern __shared__ float4 w4[];   // [16 * 256] float4
    const int tid = threadIdx.x;
    const int wid = tid >> 5, lane = tid & 31;

    const float4* wt4 = (const float4*)WT;
#pragma unroll
    for (int i = 0; i < NH; i++)
        w4[i * 256 + tid] = wt4[i * 256 + tid];
    __syncthreads();

    const float4* w0 = w4 + (size_t)wid * 256;
    const float4* w1 = w4 + (size_t)(wid + 8) * 256;
    const int rbase = blockIdx.x * LROWS;

    for (int rr = 0; rr < LROWS; rr++) {
        const int r = rbase + rr;
        const float4* rp = (const float4*)(rows + (size_t)r * DM);
        float4 v[8];
#pragma unroll
        for (int j = 0; j < 8; j++) v[j] = rp[j * 32 + lane];

        float a0 = 0.0f, a1 = 0.0f;
#pragma unroll
        for (int j = 0; j < 8; j++) {
            const float4 u0 = w0[j * 32 + lane];
            const float4 u1 = w1[j * 32 + lane];
            a0 = fmaf(v[j].x, u0.x, a0); a0 = fmaf(v[j].y, u0.y, a0);
            a0 = fmaf(v[j].z, u0.z, a0); a0 = fmaf(v[j].w, u0.w, a0);
            a1 = fmaf(v[j].x, u1.x, a1); a1 = fmaf(v[j].y, u1.y, a1);
            a1 = fmaf(v[j].z, u1.z, a1); a1 = fmaf(v[j].w, u1.w, a1);
        }
#pragma unroll
        for (int o = 16; o; o >>= 1) {
            a0 += __shfl_xor_sync(0xffffffffu, a0, o);
            a1 += __shfl_xor_sync(0xffffffffu, a1, o);
        }
        if (lane == 0) {
            const int b = r >> 11, s = r & (SS - 1);
            logits[((size_t)(b * NH + wid)) * SS + s]     = a0 * scaleF;
            logits[((size_t)(b * NH + wid + 8)) * SS + s] = a1 * scaleF;
        }
    }
}

// ---------------- pool partial (with inline softmax stats) ----------------
// 8 s-chunks x 128 bh blocks. Each block recomputes max/inv-sum over the full
// row (identical reduction structure to the old stats kernel -> same values),
// then pools its 256-s chunk: partial[bh][ck][d].
__global__ __launch_bounds__(256) void pool_partial(
    const float* __restrict__ logits, const float* __restrict__ src,
    size_t bStride, size_t hStride, size_t sStride,
    float* __restrict__ partial)
{
    const int bid = blockIdx.x;
    const int bh = bid >> 3, ck = bid & 7;
    const int b = bh >> 4, h = bh & 15;
    const float* lg = logits + (size_t)bh * SS;

    const int tid = threadIdx.x;
    const int warp = tid >> 5, lane = tid & 31;

    __shared__ float redm[8], reds[8];
    __shared__ float s_mx, s_inv;
    __shared__ float4 red4[16][16];

    // stats over the full row (matches old softmax_stats reduction exactly)
    float m = -1e30f;
    for (int s = tid; s < SS; s += 256) m = fmaxf(m, lg[s]);
#pragma unroll
    for (int o = 16; o; o >>= 1) m = fmaxf(m, __shfl_xor_sync(0xffffffffu, m, o));
    if (lane == 0) redm[warp] = m;
    __syncthreads();
    if (tid == 0) {
        float mm = redm[0];
#pragma unroll
        for (int i = 1; i < 8; i++) mm = fmaxf(mm, redm[i]);
        s_mx = mm;
    }
    __syncthreads();
    const float mx = s_mx;

    float sum = 0.0f;
    for (int s = tid; s < SS; s += 256) sum += __expf(lg[s] - mx);
#pragma unroll
    for (int o = 16; o; o >>= 1) sum += __shfl_xor_sync(0xffffffffu, sum, o);
    if (lane == 0) reds[warp] = sum;
    __syncthreads();
    if (tid == 0) {
        float ss = 0.0f;
#pragma unroll
        for (int i = 0; i < 8; i++) ss += reds[i];
        s_inv = 1.0f / ss;
    }
    __syncthreads();
    const float inv = s_inv;

    // pooling over this block's 256-s chunk
    const int d4 = tid & 15, sg = tid >> 4;
    const int s0 = ck * 256;
    const float* sp = src + (size_t)b * bStride + (size_t)h * hStride + d4 * 4;
    float4 acc = make_float4(0.f, 0.f, 0.f, 0.f);
#pragma unroll
    for (int i = 0; i < 16; i++) {
        const int s = s0 + sg + i * 16;
        const float w = __expf(lg[s] - mx) * inv;
        const float4 v = *(const float4*)(sp + (size_t)s * sStride);
        acc.x = fmaf(w, v.x, acc.x); acc.y = fmaf(w, v.y, acc.y);
        acc.z = fmaf(w, v.z, acc.z); acc.w = fmaf(w, v.w, acc.w);
    }
    red4[sg][d4] = acc;
    __syncthreads();
    if (sg == 0) {
        float4 t = red4[0][d4];
#pragma unroll
        for (int g = 1; g < 16; g++) {
            const float4 u = red4[g][d4];
            t.x += u.x; t.y += u.y; t.z += u.z; t.w += u.w;
        }
        *(float4*)(partial + (size_t)bid * DH + d4 * 4) = t;
    }
}

// ---------------- pool reduce: sum 8 chunks ----------------
__global__ __launch_bounds__(64) void pool_reduce(
    const float* __restrict__ partial, float* __restrict__ out)
{
    const int bh = blockIdx.x, d = threadIdx.x;
    const float* p = partial + (size_t)bh * 8 * DH + d;
    float t = 0.0f;
#pragma unroll
    for (int ck = 0; ck < 8; ck++) t += p[ck * DH];
    out[(size_t)bh * DH + d] = t;
}

// ---------------------------------------------------------------------------
extern "C" void kernel_launch(void* const* d_in, const int* in_sizes, int n_in,
                              void* d_out, int out_size)
{
    const float* Q_seq = (const float*)d_in[0];
    const float* K_seq = (const float*)d_in[1];
    const float* WQ = (const float*)d_in[3];
    const float* WK = (const float*)d_in[4];
    const float* Wa = (const float*)d_in[5];
    const float* Wb = (const float*)d_in[6];
    const float* WP = (const float*)d_in[7];
    float* out = (float*)d_out;

    float *pQ, *pQAK, *pWTq, *pWTk, *pWTp, *pWT3, *pLg, *pQg, *pKg;
    float *pWaT, *pWbT, *pPart;
    cudaGetSymbolAddress((void**)&pQ,   g_Q);
    cudaGetSymbolAddress((void**)&pQAK, g_QAK);
    cudaGetSymbolAddress((void**)&pWTq, g_WTq);
    cudaGetSymbolAddress((void**)&pWTk, g_WTk);
    cudaGetSymbolAddress((void**)&pWTp, g_WTp);
    cudaGetSymbolAddress((void**)&pWT3, g_WT3);
    cudaGetSymbolAddress((void**)&pLg,  g_logits);
    cudaGetSymbolAddress((void**)&pQg,  g_qglob);
    cudaGetSymbolAddress((void**)&pKg,  g_kglob);
    cudaGetSymbolAddress((void**)&pWaT, g_WaT);
    cudaGetSymbolAddress((void**)&pWbT, g_WbT);
    cudaGetSymbolAddress((void**)&pPart, g_part);

    cudaFuncSetAttribute(gemm_mma<0>, cudaFuncAttributeMaxDynamicSharedMemorySize, DYN_SMEM);
    cudaFuncSetAttribute(gemm_mma<1>, cudaFuncAttributeMaxDynamicSharedMemorySize, DYN_SMEM);
    cudaFuncSetAttribute(gemm_mma<2>, cudaFuncAttributeMaxDynamicSharedMemorySize, DYN_SMEM);
    cudaFuncSetAttribute(row_logits_sm, cudaFuncAttributeMaxDynamicSharedMemorySize, LOGIT_SMEM);

    const float scaleF = 0.125f;
    const dim3 ggrid(DM / 128, MROWS / 128);     // (8, 128)
    const dim3 tgrid3(32, 32, 3), tblk(32, 8);

    // 0. all weight prep (2 launches)
    transpose_w2<<<dim3((DM * NH + 255) / 256, 2), 256>>>(Wa, Wb, pWaT, pWbT);
    transpose_k3<<<tgrid3, tblk>>>(WQ, WK, WP, pWTq, pWTk, pWTp);

    // 1. Q = Q_seq @ WQ
    gemm_mma<0><<<ggrid, 128, DYN_SMEM>>>(Q_seq, pWTq, pQ, nullptr);

    // 2. alpha = softmax(Q @ Wa * scale); q_glob = pool(alpha, Qh)
    row_logits_sm<<<MROWS / LROWS, 256, LOGIT_SMEM>>>(pQ, pWaT, pLg, scaleF);
    pool_partial<<<NB * NH * 8, 256>>>(pLg, pQ,
                                       (size_t)SS * DM, (size_t)DH, (size_t)DM, pPart);
    pool_reduce<<<NB * NH, 64>>>(pPart, pQg);

    // 3. QAK = (K_seq @ WK) * q_glob, scattered to [b,h,s,dh]
    gemm_mma<1><<<ggrid, 128, DYN_SMEM>>>(K_seq, pWTk, pQAK, pQg);

    // 4. beta = softmax(QAK_D @ Wb * scale); k_glob = pool(beta, QAK)
    row_logits_sm<<<MROWS / LROWS, 256, LOGIT_SMEM>>>(pQAK, pWbT, pLg, scaleF);
    pool_partial<<<NB * NH * 8, 256>>>(pLg, pQAK,
                                       (size_t)NH * SS * DH, (size_t)SS * DH, (size_t)DH, pPart);
    pool_reduce<<<NB * NH, 64>>>(pPart, pKg);

    // 5. out = Q @ (diag(kg_b) WP) + Q
    scale_wt8<<<(unsigned)((size_t)NB * DM * DM / 4 / 256), 256>>>(
        (const float4*)pWTp, pKg, (float4*)pWT3);
    gemm_mma<2><<<ggrid, 128, DYN_SMEM>>>(pQ, pWT3, out, pQ);
}

// round 17
// speedup vs baseline: 1.1360x; 1.0892x over previous
#include <cuda_runtime.h>
#include <cstdint>
#include <math.h>

#define NB 8
#define SS 2048
#define DM 1024
#define NH 16
#define DH 64
#define MROWS (NB * SS)
#define ELEMS ((size_t)MROWS * DM)

__device__ float g_Q[ELEMS];             // Q = Q_seq @ WQ (fp32)
__device__ float g_QAK[ELEMS];           // QAK [b,h,s,dh]
__device__ float g_WTq[DM * DM];         // rna(WQ^T)
__device__ float g_WTk[DM * DM];         // rna(WK^T)
__device__ float g_WTp[DM * DM];         // WP^T (raw)
__device__ float g_WT3[(size_t)NB * DM * DM]; // per-batch rna(kg_b * WP^T)
__device__ float g_logits[NB * NH * SS];
__device__ float g_qglob[NB * DM];
__device__ float g_kglob[NB * DM];
__device__ float g_WaT[NH * DM];         // rna(Wa^T)
__device__ float g_WbT[NH * DM];         // rna(Wb^T)
__device__ float g_part[NB * NH * 8 * DH];

// ---------------- helpers ----------------
__device__ __forceinline__ uint32_t smem_u32(const void* p) {
    uint32_t a;
    asm("{ .reg .u64 t; cvta.to.shared.u64 t, %1; cvt.u32.u64 %0, t; }" : "=r"(a) : "l"(p));
    return a;
}
__device__ __forceinline__ void cp_async16(uint32_t s, const void* g) {
    asm volatile("cp.async.cg.shared.global [%0], [%1], 16;" :: "r"(s), "l"(g));
}
__device__ __forceinline__ void cp_commit() { asm volatile("cp.async.commit_group;" ::: "memory"); }
template <int N> __device__ __forceinline__ void cp_wait() {
    asm volatile("cp.async.wait_group %0;" :: "n"(N) : "memory");
}
__device__ __forceinline__ float rna_tf32(float x) {
    float r;
    asm("cvt.rna.tf32.f32 %0, %1;" : "=f"(r) : "f"(x));
    return r;
}
__device__ __forceinline__ void mma_tf32(float* c, const uint32_t* a, const uint32_t* b) {
    asm volatile(
        "mma.sync.aligned.m16n8k8.row.col.f32.tf32.tf32.f32 "
        "{%0,%1,%2,%3}, {%4,%5,%6,%7}, {%8,%9}, {%0,%1,%2,%3};"
        : "+f"(c[0]), "+f"(c[1]), "+f"(c[2]), "+f"(c[3])
        : "r"(a[0]), "r"(a[1]), "r"(a[2]), "r"(a[3]), "r"(b[0]), "r"(b[1]));
}

// ---------------- mma.sync tf32 GEMM: 128 threads, warp tile 64x64 (R14 verbatim) ----------------
#define BKF 32
#define ASTR 36
#define TILE_F (128 * ASTR)
#define STAGE_F (2 * TILE_F)
#define NST 3
#define KITERS (DM / BKF)
#define DYN_SMEM (NST * STAGE_F * 4)

// MODE 0: plain store. MODE 1: scale by aux[b,n], scatter to [b,h,s,dh].
// MODE 2: + aux residual, B selected per batch (Bt + b*DM*DM).
template <int MODE>
__global__ __launch_bounds__(128, 2) void gemm_mma(
    const float* __restrict__ A, const float* __restrict__ Bt_in,
    float* __restrict__ C, const float* __restrict__ aux)
{
    extern __shared__ float sm[];
    const uint32_t sbase = smem_u32(sm);
    const int tid = threadIdx.x;
    const int wid = tid >> 5, lane = tid & 31;
    const int warpM = wid & 1, warpN = wid >> 1;      // 2 x 2 warp grid, tile 64x64
    const int grp = lane >> 2, qid = lane & 3;
    const int rowM = blockIdx.y * 128, rowN = blockIdx.x * 128;
    const int bB = rowM >> 11;
    const float* Bt = (MODE == 2) ? Bt_in + (size_t)bB * DM * DM : Bt_in;

    float acc[4][8][4];
#pragma unroll
    for (int i = 0; i < 4; i++)
#pragma unroll
        for (int j = 0; j < 8; j++)
#pragma unroll
            for (int l = 0; l < 4; l++) acc[i][j][l] = 0.0f;

    auto prefetch = [&](int kt, int slot) {
        const uint32_t sA = sbase + (uint32_t)slot * STAGE_F * 4;
        const uint32_t sB = sA + TILE_F * 4;
        const int kbase = kt * BKF;
#pragma unroll
        for (int j = 0; j < 8; j++) {
            const int t = tid + j * 128;
            const int row = t >> 3, g = t & 7;
            cp_async16(sA + (uint32_t)(row * ASTR + g * 4) * 4,
                       A + (size_t)(rowM + row) * DM + kbase + g * 4);
        }
#pragma unroll
        for (int j = 0; j < 8; j++) {
            const int t = tid + j * 128;
            const int row = t >> 3, g = t & 7;
            cp_async16(sB + (uint32_t)(row * ASTR + g * 4) * 4,
                       Bt + (size_t)(rowN + row) * DM + kbase + g * 4);
        }
        cp_commit();
    };

    prefetch(0, 0);
    prefetch(1, 1);

    for (int kt = 0; kt < KITERS; kt++) {
        if (kt < KITERS - 1) cp_wait<1>(); else cp_wait<0>();
        __syncthreads();
        if (kt + 2 < KITERS) prefetch(kt + 2, (kt + 2) % NST);

        const float* As = sm + (kt % NST) * STAGE_F;
        const float* Bs = As + TILE_F;
#pragma unroll
        for (int ks = 0; ks < 4; ks++) {
            const int c = ks * 8 + qid;
            uint32_t afr[4][4], bfr[8][2];
#pragma unroll
            for (int mt = 0; mt < 4; mt++) {
                const int r = warpM * 64 + mt * 16 + grp;
                afr[mt][0] = __float_as_uint(As[r * ASTR + c]);
                afr[mt][1] = __float_as_uint(As[(r + 8) * ASTR + c]);
                afr[mt][2] = __float_as_uint(As[r * ASTR + c + 4]);
                afr[mt][3] = __float_as_uint(As[(r + 8) * ASTR + c + 4]);
            }
#pragma unroll
            for (int nt = 0; nt < 8; nt++) {
                const int n = warpN * 64 + nt * 8 + grp;
                bfr[nt][0] = __float_as_uint(Bs[n * ASTR + c]);
                bfr[nt][1] = __float_as_uint(Bs[n * ASTR + c + 4]);
            }
#pragma unroll
            for (int mt = 0; mt < 4; mt++)
#pragma unroll
                for (int nt = 0; nt < 8; nt++)
                    mma_tf32(acc[mt][nt], afr[mt], bfr[nt]);
        }
    }

    // Epilogue
#pragma unroll
    for (int mt = 0; mt < 4; mt++) {
        const int r0 = rowM + warpM * 64 + mt * 16 + grp;
        const int r1 = r0 + 8;
        const int s0 = r0 & (SS - 1), s1 = r1 & (SS - 1);
#pragma unroll
        for (int nt = 0; nt < 8; nt++) {
            const int n = rowN + warpN * 64 + nt * 8 + qid * 2;
            const float* a4 = acc[mt][nt];
            if (MODE == 0) {
                *(float2*)(C + (size_t)r0 * DM + n) = make_float2(a4[0], a4[1]);
                *(float2*)(C + (size_t)r1 * DM + n) = make_float2(a4[2], a4[3]);
            } else if (MODE == 1) {
                const int h = n >> 6, d = n & 63;
                const float2 g = *(const float2*)(aux + (size_t)bB * DM + n);
                float* base = C + (((size_t)(bB * NH + h)) << 17) + d;  // *2048*64
                *(float2*)(base + (size_t)s0 * DH) = make_float2(a4[0] * g.x, a4[1] * g.y);
                *(float2*)(base + (size_t)s1 * DH) = make_float2(a4[2] * g.x, a4[3] * g.y);
            } else {
                const float2 q0 = *(const float2*)(aux + (size_t)r0 * DM + n);
                const float2 q1 = *(const float2*)(aux + (size_t)r1 * DM + n);
                *(float2*)(C + (size_t)r0 * DM + n) = make_float2(a4[0] + q0.x, a4[1] + q0.y);
                *(float2*)(C + (size_t)r1 * DM + n) = make_float2(a4[2] + q1.x, a4[3] + q1.y);
            }
        }
    }
}

// ---------------- logits GEMM: [16384,1024] x [1024,16] -> logits[b,e,s] ----------------
// BM=128, BN=16, BK=32, 128 threads (4 warps x 32 rows, each warp N=16).
// A raw fp32 (HW tf32 truncation); Bt = rna-rounded [16][1024] weight.
#define LTILE_A (128 * ASTR)
#define LTILE_B (16 * ASTR)
#define LSTAGE_F (LTILE_A + LTILE_B)
#define LDYN (NST * LSTAGE_F * 4)

__global__ __launch_bounds__(128, 2) void logits_mma(
    const float* __restrict__ A, const float* __restrict__ Bt,
    float* __restrict__ logits, float scaleF)
{
    extern __shared__ float sm[];
    const uint32_t sbase = smem_u32(sm);
    const int tid = threadIdx.x;
    const int wid = tid >> 5, lane = tid & 31;
    const int grp = lane >> 2, qid = lane & 3;
    const int rowM = blockIdx.x * 128;
    const int bB = rowM >> 11;

    float acc[2][2][4];
#pragma unroll
    for (int i = 0; i < 2; i++)
#pragma unroll
        for (int j = 0; j < 2; j++)
#pragma unroll
            for (int l = 0; l < 4; l++) acc[i][j][l] = 0.0f;

    auto prefetch = [&](int kt, int slot) {
        const uint32_t sA = sbase + (uint32_t)slot * LSTAGE_F * 4;
        const uint32_t sB = sA + LTILE_A * 4;
        const int kbase = kt * BKF;
#pragma unroll
        for (int j = 0; j < 8; j++) {
            const int t = tid + j * 128;
            const int row = t >> 3, g = t & 7;
            cp_async16(sA + (uint32_t)(row * ASTR + g * 4) * 4,
                       A + (size_t)(rowM + row) * DM + kbase + g * 4);
        }
        {   // B: 16 rows x 8 float4 = 128 loads, one per thread
            const int row = tid >> 3, g = tid & 7;
            cp_async16(sB + (uint32_t)(row * ASTR + g * 4) * 4,
                       Bt + (size_t)row * DM + kbase + g * 4);
        }
        cp_commit();
    };

    prefetch(0, 0);
    prefetch(1, 1);

    for (int kt = 0; kt < KITERS; kt++) {
        if (kt < KITERS - 1) cp_wait<1>(); else cp_wait<0>();
        __syncthreads();
        if (kt + 2 < KITERS) prefetch(kt + 2, (kt + 2) % NST);

        const float* As = sm + (kt % NST) * LSTAGE_F;
        const float* Bs = As + LTILE_A;
#pragma unroll
        for (int ks = 0; ks < 4; ks++) {
            const int c = ks * 8 + qid;
            uint32_t afr[2][4], bfr[2][2];
#pragma unroll
            for (int mt = 0; mt < 2; mt++) {
                const int r = wid * 32 + mt * 16 + grp;
                afr[mt][0] = __float_as_uint(As[r * ASTR + c]);
                afr[mt][1] = __float_as_uint(As[(r + 8) * ASTR + c]);
                afr[mt][2] = __float_as_uint(As[r * ASTR + c + 4]);
                afr[mt][3] = __float_as_uint(As[(r + 8) * ASTR + c + 4]);
            }
#pragma unroll
            for (int nt = 0; nt < 2; nt++) {
                const int n = nt * 8 + grp;
                bfr[nt][0] = __float_as_uint(Bs[n * ASTR + c]);
                bfr[nt][1] = __float_as_uint(Bs[n * ASTR + c + 4]);
            }
#pragma unroll
            for (int mt = 0; mt < 2; mt++)
#pragma unroll
                for (int nt = 0; nt < 2; nt++)
                    mma_tf32(acc[mt][nt], afr[mt], bfr[nt]);
        }
    }

    // Epilogue: logits[(b*16+e)*SS + s] = acc * scaleF
#pragma unroll
    for (int mt = 0; mt < 2; mt++) {
        const int r0 = rowM + wid * 32 + mt * 16 + grp;
        const int r1 = r0 + 8;
        const int s0 = r0 & (SS - 1), s1 = r1 & (SS - 1);
#pragma unroll
        for (int nt = 0; nt < 2; nt++) {
            const int e = nt * 8 + qid * 2;
            const float* a4 = acc[mt][nt];
            logits[((size_t)(bB * NH + e)) * SS + s0]     = a4[0] * scaleF;
            logits[((size_t)(bB * NH + e + 1)) * SS + s0] = a4[1] * scaleF;
            logits[((size_t)(bB * NH + e)) * SS + s1]     = a4[2] * scaleF;
            logits[((size_t)(bB * NH + e + 1)) * SS + s1] = a4[3] * scaleF;
        }
    }
}

// ---------------- small kernels ----------------
// merged weight transposes: z=0 WQ->rna, z=1 WK->rna, z=2 WP->raw
__global__ void transpose_k3(
    const float* __restrict__ WQ, const float* __restrict__ WK,
    const float* __restrict__ WP,
    float* __restrict__ WTq, float* __restrict__ WTk, float* __restrict__ WTp)
{
    __shared__ float t[32][33];
    const int z = blockIdx.z;
    const float* W = (z == 0) ? WQ : (z == 1) ? WK : WP;
    float* WT      = (z == 0) ? WTq : (z == 1) ? WTk : WTp;
    const bool rna = (z < 2);

    const int x0 = blockIdx.x * 32, y0 = blockIdx.y * 32;
    const int tx = threadIdx.x, ty = threadIdx.y;  // 32 x 8
#pragma unroll
    for (int j = 0; j < 32; j += 8)
        t[ty + j][tx] = W[(size_t)(y0 + ty + j) * DM + x0 + tx];
    __syncthreads();
#pragma unroll
    for (int j = 0; j < 32; j += 8) {
        float v = t[tx][ty + j];
        WT[(size_t)(x0 + ty + j) * DM + y0 + tx] = rna ? rna_tf32(v) : v;
    }
}

// merged small-weight transposes (rna-rounded for the logits GEMM): y=0 Wa, y=1 Wb
__global__ void transpose_w2(
    const float* __restrict__ Wa, const float* __restrict__ Wb,
    float* __restrict__ WaT, float* __restrict__ WbT)
{
    const float* W = blockIdx.y ? Wb : Wa;
    float* WT      = blockIdx.y ? WbT : WaT;
    int i = blockIdx.x * 256 + threadIdx.x;
    if (i < DM * NH) {
        int j = i >> 4, e = i & 15;
        WT[e * DM + j] = rna_tf32(W[i]);
    }
}

// WT3[b][n][k] = rna( WTp[n][k] * kg[b][k] )
__global__ __launch_bounds__(256) void scale_wt8(
    const float4* __restrict__ WTp, const float* __restrict__ kg,
    float4* __restrict__ WT3)
{
    const size_t i = (size_t)blockIdx.x * 256 + threadIdx.x;  // 2M float4
    const int k4 = (int)(i & 255);
    const int b  = (int)(i >> 18);
    const float4 w = WTp[i & ((1u << 18) - 1)];
    const float4 g = *(const float4*)(kg + (size_t)b * DM + k4 * 4);
    float4 o;
    o.x = rna_tf32(w.x * g.x); o.y = rna_tf32(w.y * g.y);
    o.z = rna_tf32(w.z * g.z); o.w = rna_tf32(w.w * g.w);
    WT3[i] = o;
}

// ---------------- pool partial (with inline softmax stats) ----------------
__global__ __launch_bounds__(256) void pool_partial(
    const float* __restrict__ logits, const float* __restrict__ src,
    size_t bStride, size_t hStride, size_t sStride,
    float* __restrict__ partial)
{
    const int bid = blockIdx.x;
    const int bh = bid >> 3, ck = bid & 7;
    const int b = bh >> 4, h = bh & 15;
    const float* lg = logits + (size_t)bh * SS;

    const int tid = threadIdx.x;
    const int warp = tid >> 5, lane = tid & 31;

    __shared__ float redm[8], reds[8];
    __shared__ float s_mx, s_inv;
    __shared__ float4 red4[16][16];

    float m = -1e30f;
    for (int s = tid; s < SS; s += 256) m = fmaxf(m, lg[s]);
#pragma unroll
    for (int o = 16; o; o >>= 1) m = fmaxf(m, __shfl_xor_sync(0xffffffffu, m, o));
    if (lane == 0) redm[warp] = m;
    __syncthreads();
    if (tid == 0) {
        float mm = redm[0];
#pragma unroll
        for (int i = 1; i < 8; i++) mm = fmaxf(mm, redm[i]);
        s_mx = mm;
    }
    __syncthreads();
    const float mx = s_mx;

    float sum = 0.0f;
    for (int s = tid; s < SS; s += 256) sum += __expf(lg[s] - mx);
#pragma unroll
    for (int o = 16; o; o >>= 1) sum += __shfl_xor_sync(0xffffffffu, sum, o);
    if (lane == 0) reds[warp] = sum;
    __syncthreads();
    if (tid == 0) {
        float ss = 0.0f;
#pragma unroll
        for (int i = 0; i < 8; i++) ss += reds[i];
        s_inv = 1.0f / ss;
    }
    __syncthreads();
    const float inv = s_inv;

    const int d4 = tid & 15, sg = tid >> 4;
    const int s0 = ck * 256;
    const float* sp = src + (size_t)b * bStride + (size_t)h * hStride + d4 * 4;
    float4 acc = make_float4(0.f, 0.f, 0.f, 0.f);
#pragma unroll
    for (int i = 0; i < 16; i++) {
        const int s = s0 + sg + i * 16;
        const float w = __expf(lg[s] - mx) * inv;
        const float4 v = *(const float4*)(sp + (size_t)s * sStride);
        acc.x = fmaf(w, v.x, acc.x); acc.y = fmaf(w, v.y, acc.y);
        acc.z = fmaf(w, v.z, acc.z); acc.w = fmaf(w, v.w, acc.w);
    }
    red4[sg][d4] = acc;
    __syncthreads();
    if (sg == 0) {
        float4 t = red4[0][d4];
#pragma unroll
        for (int g = 1; g < 16; g++) {
            const float4 u = red4[g][d4];
            t.x += u.x; t.y += u.y; t.z += u.z; t.w += u.w;
        }
        *(float4*)(partial + (size_t)bid * DH + d4 * 4) = t;
    }
}

// ---------------- pool reduce: sum 8 chunks ----------------
__global__ __launch_bounds__(64) void pool_reduce(
    const float* __restrict__ partial, float* __restrict__ out)
{
    const int bh = blockIdx.x, d = threadIdx.x;
    const float* p = partial + (size_t)bh * 8 * DH + d;
    float t = 0.0f;
#pragma unroll
    for (int ck = 0; ck < 8; ck++) t += p[ck * DH];
    out[(size_t)bh * DH + d] = t;
}

// ---------------------------------------------------------------------------
extern "C" void kernel_launch(void* const* d_in, const int* in_sizes, int n_in,
                              void* d_out, int out_size)
{
    const float* Q_seq = (const float*)d_in[0];
    const float* K_seq = (const float*)d_in[1];
    const float* WQ = (const float*)d_in[3];
    const float* WK = (const float*)d_in[4];
    const float* Wa = (const float*)d_in[5];
    const float* Wb = (const float*)d_in[6];
    const float* WP = (const float*)d_in[7];
    float* out = (float*)d_out;

    float *pQ, *pQAK, *pWTq, *pWTk, *pWTp, *pWT3, *pLg, *pQg, *pKg;
    float *pWaT, *pWbT, *pPart;
    cudaGetSymbolAddress((void**)&pQ,   g_Q);
    cudaGetSymbolAddress((void**)&pQAK, g_QAK);
    cudaGetSymbolAddress((void**)&pWTq, g_WTq);
    cudaGetSymbolAddress((void**)&pWTk, g_WTk);
    cudaGetSymbolAddress((void**)&pWTp, g_WTp);
    cudaGetSymbolAddress((void**)&pWT3, g_WT3);
    cudaGetSymbolAddress((void**)&pLg,  g_logits);
    cudaGetSymbolAddress((void**)&pQg,  g_qglob);
    cudaGetSymbolAddress((void**)&pKg,  g_kglob);
    cudaGetSymbolAddress((void**)&pWaT, g_WaT);
    cudaGetSymbolAddress((void**)&pWbT, g_WbT);
    cudaGetSymbolAddress((void**)&pPart, g_part);

    cudaFuncSetAttribute(gemm_mma<0>, cudaFuncAttributeMaxDynamicSharedMemorySize, DYN_SMEM);
    cudaFuncSetAttribute(gemm_mma<1>, cudaFuncAttributeMaxDynamicSharedMemorySize, DYN_SMEM);
    cudaFuncSetAttribute(gemm_mma<2>, cudaFuncAttributeMaxDynamicSharedMemorySize, DYN_SMEM);
    cudaFuncSetAttribute(logits_mma,  cudaFuncAttributeMaxDynamicSharedMemorySize, LDYN);

    const float scaleF = 0.125f;
    const dim3 ggrid(DM / 128, MROWS / 128);     // (8, 128)
    const dim3 tgrid3(32, 32, 3), tblk(32, 8);

    // 0. weight prep (2 launches)
    transpose_w2<<<dim3((DM * NH + 255) / 256, 2), 256>>>(Wa, Wb, pWaT, pWbT);
    transpose_k3<<<tgrid3, tblk>>>(WQ, WK, WP, pWTq, pWTk, pWTp);

    // 1. Q = Q_seq @ WQ
    gemm_mma<0><<<ggrid, 128, DYN_SMEM>>>(Q_seq, pWTq, pQ, nullptr);

    // 2. alpha = softmax(Q @ Wa * scale); q_glob = pool(alpha, Qh)
    logits_mma<<<MROWS / 128, 128, LDYN>>>(pQ, pWaT, pLg, scaleF);
    pool_partial<<<NB * NH * 8, 256>>>(pLg, pQ,
                                       (size_t)SS * DM, (size_t)DH, (size_t)DM, pPart);
    pool_reduce<<<NB * NH, 64>>>(pPart, pQg);

    // 3. QAK = (K_seq @ WK) * q_glob, scattered to [b,h,s,dh]
    gemm_mma<1><<<ggrid, 128, DYN_SMEM>>>(K_seq, pWTk, pQAK, pQg);

    // 4. beta = softmax(QAK_D @ Wb * scale); k_glob = pool(beta, QAK)
    logits_mma<<<MROWS / 128, 128, LDYN>>>(pQAK, pWbT, pLg, scaleF);
    pool_partial<<<NB * NH * 8, 256>>>(pLg, pQAK,
                                       (size_t)NH * SS * DH, (size_t)SS * DH, (size_t)DH, pPart);
    pool_reduce<<<NB * NH, 64>>>(pPart, pKg);

    // 5. out = Q @ (diag(kg_b) WP) + Q
    scale_wt8<<<(unsigned)((size_t)NB * DM * DM / 4 / 256), 256>>>(
        (const float4*)pWTp, pKg, (float4*)pWT3);
    gemm_mma<2><<<ggrid, 128, DYN_SMEM>>>(pQ, pWT3, out, pQ);
}